// round 5
// baseline (speedup 1.0000x reference)
#include <cuda_runtime.h>
#include <math.h>

#define NB 4
#define NT 1024
#define NE 1024
#define NH 16
#define ND 64
#define NE3 3072
#define NM (NB * NT)   // 4096

// Single scratch block: Q | K | V | O, each (2,B,H,T,D) fp32 = 32 MB.
#define SEG (2u * NB * NH * NT * ND)
__device__ float g_scratch[4u * SEG];
#define G_Q (g_scratch)
#define G_K (g_scratch + SEG)
#define G_V (g_scratch + 2u * SEG)
#define G_O (g_scratch + 3u * SEG)

// ---------------------------------------------------------------------------
// QKV GEMM: C[m,n] = sum_k A[m,k] * W[n,k]; scatter C into q/k/v buffers.
// A: (4096, 1024) row-major, W: (3072, 1024) row-major.
// n -> (dd, kc, h): n = dd*48 + kc*16 + h
// ---------------------------------------------------------------------------
__global__ __launch_bounds__(256) void qkv_gemm(
    const float* __restrict__ x, const float* __restrict__ y,
    const float* __restrict__ W1, const float* __restrict__ W2) {
  const int s = blockIdx.z;
  const float* __restrict__ A = s ? y : x;
  const float* __restrict__ W = s ? W2 : W1;
  const int n0 = blockIdx.x * 128;
  const int m0 = blockIdx.y * 128;

  __shared__ float As[8][128];
  __shared__ float Bs[8][128];

  const int tid = threadIdx.x;
  const int tx = tid & 15;
  const int ty = tid >> 4;
  const int lrow = tid >> 1;
  const int lk4 = (tid & 1) << 2;

  float acc[8][8];
#pragma unroll
  for (int i = 0; i < 8; i++)
#pragma unroll
    for (int j = 0; j < 8; j++) acc[i][j] = 0.f;

  const float* Aptr = A + (size_t)(m0 + lrow) * NE + lk4;
  const float* Wptr = W + (size_t)(n0 + lrow) * NE + lk4;

  for (int k0 = 0; k0 < NE; k0 += 8) {
    float4 av = *(const float4*)(Aptr + k0);
    float4 wv = *(const float4*)(Wptr + k0);
    As[lk4 + 0][lrow] = av.x; As[lk4 + 1][lrow] = av.y;
    As[lk4 + 2][lrow] = av.z; As[lk4 + 3][lrow] = av.w;
    Bs[lk4 + 0][lrow] = wv.x; Bs[lk4 + 1][lrow] = wv.y;
    Bs[lk4 + 2][lrow] = wv.z; Bs[lk4 + 3][lrow] = wv.w;
    __syncthreads();
#pragma unroll
    for (int kk = 0; kk < 8; kk++) {
      float4 a0 = *(const float4*)&As[kk][ty * 8];
      float4 a1 = *(const float4*)&As[kk][ty * 8 + 4];
      float4 b0 = *(const float4*)&Bs[kk][tx * 8];
      float4 b1 = *(const float4*)&Bs[kk][tx * 8 + 4];
      float a[8], b[8];
      a[0] = a0.x; a[1] = a0.y; a[2] = a0.z; a[3] = a0.w;
      a[4] = a1.x; a[5] = a1.y; a[6] = a1.z; a[7] = a1.w;
      b[0] = b0.x; b[1] = b0.y; b[2] = b0.z; b[3] = b0.w;
      b[4] = b1.x; b[5] = b1.y; b[6] = b1.z; b[7] = b1.w;
#pragma unroll
      for (int i = 0; i < 8; i++)
#pragma unroll
        for (int j = 0; j < 8; j++) acc[i][j] += a[i] * b[j];
    }
    __syncthreads();
  }

  // Scatter epilogue into (s,b,h,t,d) q/k/v layout.
#pragma unroll
  for (int i = 0; i < 8; i++) {
    int m = m0 + ty * 8 + i;
    int bb = m >> 10;
    int t = m & 1023;
#pragma unroll
    for (int j = 0; j < 8; j++) {
      int n = n0 + tx * 8 + j;
      int dd = n / 48;
      int rem = n - dd * 48;
      int kc = rem >> 4;
      int h = rem & 15;
      float* base = (kc == 0) ? G_Q : (kc == 1) ? G_K : G_V;
      base[((((size_t)s * NB + bb) * NH + h) * NT + t) * ND + dd] = acc[i][j];
    }
  }
}

// ---------------------------------------------------------------------------
// Flash attention: per (stream s, b, h), Br=64 query rows per block,
// loop over 32 KV tiles of 32 rows each, online softmax.
// Output stream s: Q = G_Q[1-s], K = G_K[s], V = G_V[s].
// Static smem: 43,520 B (under 48KB -> no cudaFuncSetAttribute needed).
// ---------------------------------------------------------------------------
#define BC 32

__global__ __launch_bounds__(256) void attn_kernel() {
  __shared__ float Qs[64 * 68];
  __shared__ float Ks[BC * 68];
  __shared__ float Ps[64 * 36];
  __shared__ float Vs[BC * 64];

  const int s = blockIdx.z;
  const int bh = blockIdx.y;    // 0..63
  const int bb = bh >> 4;
  const int h = bh & 15;
  const int q0 = blockIdx.x * 64;

  const size_t qoff = (((size_t)(1 - s) * NB + bb) * NH + h) * NT * ND;
  const size_t kvoff = (((size_t)s * NB + bb) * NH + h) * NT * ND;
  const float* __restrict__ Qg = G_Q + qoff;
  const float* __restrict__ Kg = G_K + kvoff;
  const float* __restrict__ Vg = G_V + kvoff;
  float* __restrict__ Og = G_O + kvoff;

  const int tid = threadIdx.x;
  const int row = tid >> 2;     // 0..63
  const int part = tid & 3;     // 0..3

  // KV loader mapping: 256 threads cover 32 rows x 64 floats (2 float4 each).
  const int krow = tid >> 3;          // 0..31
  const int kcol = (tid & 7) * 8;     // 0,8,...,56

  // Load Q tile (64x64), padded stride 68.
  {
    const float4* src = (const float4*)&Qg[(size_t)(q0 + row) * ND + part * 16];
    float4* dst = (float4*)&Qs[row * 68 + part * 16];
    dst[0] = src[0]; dst[1] = src[1]; dst[2] = src[2]; dst[3] = src[3];
  }
  __syncthreads();

  float m_i = -1e30f;
  float l_i = 0.f;
  float acc[16];
#pragma unroll
  for (int i = 0; i < 16; i++) acc[i] = 0.f;

  for (int kt = 0; kt < NT / BC; kt++) {
    // Load K, V tiles (32 x 64 each).
    {
      const float4* ksrc = (const float4*)&Kg[(size_t)(kt * BC + krow) * ND + kcol];
      float4* kdst = (float4*)&Ks[krow * 68 + kcol];
      kdst[0] = ksrc[0]; kdst[1] = ksrc[1];
      const float4* vsrc = (const float4*)&Vg[(size_t)(kt * BC + krow) * ND + kcol];
      float4* vdst = (float4*)&Vs[krow * 64 + kcol];
      vdst[0] = vsrc[0]; vdst[1] = vsrc[1];
    }
    __syncthreads();

    // Scores: each thread computes 8 of the 32 key columns for its row.
    float sv[8];
    const float4* qr = (const float4*)&Qs[row * 68];
#pragma unroll
    for (int jc = 0; jc < 8; jc++) {
      const int j = jc * 4 + part;
      const float4* kr = (const float4*)&Ks[j * 68];
      float sum = 0.f;
#pragma unroll
      for (int d4 = 0; d4 < 16; d4++) {
        float4 qa = qr[d4];
        float4 kb = kr[d4];
        sum += qa.x * kb.x + qa.y * kb.y + qa.z * kb.z + qa.w * kb.w;
      }
      sv[jc] = sum * 0.125f;
    }

    // Row max across the 4 lanes of this row-group.
    float mloc = sv[0];
#pragma unroll
    for (int jc = 1; jc < 8; jc++) mloc = fmaxf(mloc, sv[jc]);
    mloc = fmaxf(mloc, __shfl_xor_sync(0xffffffffu, mloc, 1));
    mloc = fmaxf(mloc, __shfl_xor_sync(0xffffffffu, mloc, 2));
    const float m_new = fmaxf(m_i, mloc);

    float psum = 0.f;
#pragma unroll
    for (int jc = 0; jc < 8; jc++) {
      float p = __expf(sv[jc] - m_new);
      Ps[row * 36 + jc * 4 + part] = p;
      psum += p;
    }
    psum += __shfl_xor_sync(0xffffffffu, psum, 1);
    psum += __shfl_xor_sync(0xffffffffu, psum, 2);

    const float alpha = __expf(m_i - m_new);
    m_i = m_new;
    l_i = l_i * alpha + psum;
#pragma unroll
    for (int i = 0; i < 16; i++) acc[i] *= alpha;
    __syncwarp();

    // O += P * V  (thread owns dcols part*16 .. part*16+15)
#pragma unroll 8
    for (int j = 0; j < BC; j++) {
      float p = Ps[row * 36 + j];
      const float4* vr = (const float4*)&Vs[j * 64 + part * 16];
      float4 v0 = vr[0], v1 = vr[1], v2 = vr[2], v3 = vr[3];
      acc[0]  += p * v0.x; acc[1]  += p * v0.y; acc[2]  += p * v0.z; acc[3]  += p * v0.w;
      acc[4]  += p * v1.x; acc[5]  += p * v1.y; acc[6]  += p * v1.z; acc[7]  += p * v1.w;
      acc[8]  += p * v2.x; acc[9]  += p * v2.y; acc[10] += p * v2.z; acc[11] += p * v2.w;
      acc[12] += p * v3.x; acc[13] += p * v3.y; acc[14] += p * v3.z; acc[15] += p * v3.w;
    }
    __syncthreads();
  }

  const float inv = 1.f / l_i;
  float4* odst = (float4*)&Og[(size_t)(q0 + row) * ND + part * 16];
  float4 o0, o1, o2, o3;
  o0.x = acc[0] * inv;  o0.y = acc[1] * inv;  o0.z = acc[2] * inv;  o0.w = acc[3] * inv;
  o1.x = acc[4] * inv;  o1.y = acc[5] * inv;  o1.z = acc[6] * inv;  o1.w = acc[7] * inv;
  o2.x = acc[8] * inv;  o2.y = acc[9] * inv;  o2.z = acc[10] * inv; o2.w = acc[11] * inv;
  o3.x = acc[12] * inv; o3.y = acc[13] * inv; o3.z = acc[14] * inv; o3.w = acc[15] * inv;
  odst[0] = o0; odst[1] = o1; odst[2] = o2; odst[3] = o3;
}

// ---------------------------------------------------------------------------
// Out projection: out_s[m,n] = sum_k Aflat[m,k] * Wout_s[n,k]
// Aflat[m, h*64+dd] = G_O[s][b][h][t][dd] (transpose fused into A load).
// ---------------------------------------------------------------------------
__global__ __launch_bounds__(256) void proj_gemm(
    const float* __restrict__ Wo1, const float* __restrict__ Wo2,
    float* __restrict__ out) {
  const int s = blockIdx.z;
  const float* __restrict__ W = s ? Wo2 : Wo1;
  const int n0 = blockIdx.x * 128;
  const int m0 = blockIdx.y * 128;

  __shared__ float As[8][128];
  __shared__ float Bs[8][128];

  const int tid = threadIdx.x;
  const int tx = tid & 15;
  const int ty = tid >> 4;
  const int lrow = tid >> 1;
  const int lk4 = (tid & 1) << 2;

  float acc[8][8];
#pragma unroll
  for (int i = 0; i < 8; i++)
#pragma unroll
    for (int j = 0; j < 8; j++) acc[i][j] = 0.f;

  const int m = m0 + lrow;
  const int bb = m >> 10;
  const int t = m & 1023;
  const float* Wptr = W + (size_t)(n0 + lrow) * NE + lk4;

  for (int k0 = 0; k0 < NE; k0 += 8) {
    const int k = k0 + lk4;
    const int h = k >> 6;
    const int dd = k & 63;
    float4 av = *(const float4*)&G_O[((((size_t)s * NB + bb) * NH + h) * NT + t) * ND + dd];
    float4 wv = *(const float4*)(Wptr + k0);
    As[lk4 + 0][lrow] = av.x; As[lk4 + 1][lrow] = av.y;
    As[lk4 + 2][lrow] = av.z; As[lk4 + 3][lrow] = av.w;
    Bs[lk4 + 0][lrow] = wv.x; Bs[lk4 + 1][lrow] = wv.y;
    Bs[lk4 + 2][lrow] = wv.z; Bs[lk4 + 3][lrow] = wv.w;
    __syncthreads();
#pragma unroll
    for (int kk = 0; kk < 8; kk++) {
      float4 a0 = *(const float4*)&As[kk][ty * 8];
      float4 a1 = *(const float4*)&As[kk][ty * 8 + 4];
      float4 b0 = *(const float4*)&Bs[kk][tx * 8];
      float4 b1 = *(const float4*)&Bs[kk][tx * 8 + 4];
      float a[8], b[8];
      a[0] = a0.x; a[1] = a0.y; a[2] = a0.z; a[3] = a0.w;
      a[4] = a1.x; a[5] = a1.y; a[6] = a1.z; a[7] = a1.w;
      b[0] = b0.x; b[1] = b0.y; b[2] = b0.z; b[3] = b0.w;
      b[4] = b1.x; b[5] = b1.y; b[6] = b1.z; b[7] = b1.w;
#pragma unroll
      for (int i = 0; i < 8; i++)
#pragma unroll
        for (int j = 0; j < 8; j++) acc[i][j] += a[i] * b[j];
    }
    __syncthreads();
  }

  float* obase = out + (size_t)s * NM * NE;
#pragma unroll
  for (int i = 0; i < 8; i++) {
    int mm = m0 + ty * 8 + i;
    float4* dst = (float4*)&obase[(size_t)mm * NE + n0 + tx * 8];
    float4 c0, c1;
    c0.x = acc[i][0]; c0.y = acc[i][1]; c0.z = acc[i][2]; c0.w = acc[i][3];
    c1.x = acc[i][4]; c1.y = acc[i][5]; c1.z = acc[i][6]; c1.w = acc[i][7];
    dst[0] = c0; dst[1] = c1;
  }
}

// ---------------------------------------------------------------------------

extern "C" void kernel_launch(void* const* d_in, const int* in_sizes, int n_in,
                              void* d_out, int out_size) {
  const float* x = (const float*)d_in[0];
  const float* y = (const float*)d_in[1];
  const float* Wqkv1 = (const float*)d_in[2];
  const float* Wqkv2 = (const float*)d_in[3];
  const float* Wout1 = (const float*)d_in[4];
  const float* Wout2 = (const float*)d_in[5];
  float* out = (float*)d_out;

  qkv_gemm<<<dim3(NE3 / 128, NM / 128, 2), 256>>>(x, y, Wqkv1, Wqkv2);
  attn_kernel<<<dim3(NT / 64, NB * NH, 2), 256>>>();
  proj_gemm<<<dim3(NE / 128, NM / 128, 2), 256>>>(Wout1, Wout2, out);
}

// round 11
// speedup vs baseline: 1.2646x; 1.2646x over previous
#include <cuda_runtime.h>
#include <cuda_bf16.h>
#include <cstdint>
#include <math.h>

#define NB 4
#define NT 1024
#define NE 1024
#define NH 16
#define ND 64
#define NE3 3072
#define NM 4096

// ---------------------------------------------------------------------------
// Scratch
// ---------------------------------------------------------------------------
#define SEG (2u * NB * NH * NT * ND)
__device__ float g_qkv[3u * SEG];              // Q | K | V fp32 (s,b,h,t,d)
#define G_Q (g_qkv)
#define G_K (g_qkv + SEG)
#define G_V (g_qkv + 2u * SEG)

__device__ __nv_bfloat16 g_xy_h[2u * NM * NE];
__device__ __nv_bfloat16 g_xy_l[2u * NM * NE];
__device__ __nv_bfloat16 g_wq_h[2u * NE3 * NE];
__device__ __nv_bfloat16 g_wq_l[2u * NE3 * NE];
__device__ __nv_bfloat16 g_wo_h[2u * NE * NE];
__device__ __nv_bfloat16 g_wo_l[2u * NE * NE];
__device__ __nv_bfloat16 g_ao_h[2u * NM * NE];   // attn out hi, flat [s][m][h*64+d]
__device__ __nv_bfloat16 g_ao_l[2u * NM * NE];

// ---------------------------------------------------------------------------
// fp32 -> bf16 hi/lo split
// ---------------------------------------------------------------------------
__global__ __launch_bounds__(256) void convert_split(
    const float* __restrict__ src, __nv_bfloat16* __restrict__ hi,
    __nv_bfloat16* __restrict__ lo, int n) {
  int i = blockIdx.x * 256 + threadIdx.x;
  if (i < n) {
    float v = src[i];
    __nv_bfloat16 h = __float2bfloat16(v);
    hi[i] = h;
    lo[i] = __float2bfloat16(v - __bfloat162float(h));
  }
}

// ---------------------------------------------------------------------------
// mma.sync helpers (plain sm_80+ PTX; legal under compute_103)
// ---------------------------------------------------------------------------
__device__ __forceinline__ uint32_t smem_u32(const void* p) {
  uint32_t a;
  asm("{ .reg .u64 t; cvta.to.shared.u64 t, %1; cvt.u32.u64 %0, t; }" : "=r"(a) : "l"(p));
  return a;
}

__device__ __forceinline__ void ldsm_x4(uint32_t& r0, uint32_t& r1, uint32_t& r2,
                                        uint32_t& r3, uint32_t addr) {
  asm volatile("ldmatrix.sync.aligned.m8n8.x4.shared.b16 {%0,%1,%2,%3}, [%4];"
               : "=r"(r0), "=r"(r1), "=r"(r2), "=r"(r3) : "r"(addr));
}

__device__ __forceinline__ void mma16816(float* d, const uint32_t* a,
                                         uint32_t b0, uint32_t b1) {
  asm volatile(
      "mma.sync.aligned.m16n8k16.row.col.f32.bf16.bf16.f32 "
      "{%0,%1,%2,%3}, {%4,%5,%6,%7}, {%8,%9}, {%0,%1,%2,%3};"
      : "+f"(d[0]), "+f"(d[1]), "+f"(d[2]), "+f"(d[3])
      : "r"(a[0]), "r"(a[1]), "r"(a[2]), "r"(a[3]), "r"(b0), "r"(b1));
}

// ---------------------------------------------------------------------------
// GEMM mainloop: 128x128 CTA tile, K=1024 in 16 chunks of 64.
// smem tiles padded to 144B row stride (72 bf16) -> conflict-free ldmatrix.
// Warp w: rows (w>>1)*32, cols (w&1)*64. 2 m-tiles x 8 n-tiles of m16n8.
// acc = Ah*Bh + Ah*Bl + Al*Bh (fp32 accum).
// ---------------------------------------------------------------------------
#define TSTRIDE 144
#define TILE_B (128 * TSTRIDE)      // 18432
#define OFF_AH 0
#define OFF_AL TILE_B
#define OFF_BH (2 * TILE_B)
#define OFF_BL (3 * TILE_B)
#define GEMM_SMEM (4 * TILE_B)      // 73728

__device__ __forceinline__ void load_tile(const __nv_bfloat16* g, int row0,
                                          int k0, char* dst, int tid) {
  const int row = tid >> 1;
  const int half = (tid & 1) * 32;  // bf16 offset within row
  const uint4* src = (const uint4*)(g + (size_t)(row0 + row) * NE + k0 + half);
  uint4* d = (uint4*)(dst + row * TSTRIDE + half * 2);
  d[0] = src[0]; d[1] = src[1]; d[2] = src[2]; d[3] = src[3];
}

__device__ __forceinline__ void mma_mainloop(
    const __nv_bfloat16* Ah, const __nv_bfloat16* Al,
    const __nv_bfloat16* Bh, const __nv_bfloat16* Bl,
    int m0, int n0, char* sm, float acc[2][8][4]) {
  const int tid = threadIdx.x;
  const int lane = tid & 31;
  const int w = tid >> 5;
  const int m_base = (w >> 1) * 32;
  const int n_base = (w & 1) * 64;

  const uint32_t sbase = smem_u32(sm);
  // ldmatrix lane-address components
  const uint32_t a_lane = (uint32_t)(lane & 15) * TSTRIDE + (uint32_t)(lane >> 4) * 16;
  const uint32_t b_lane =
      (uint32_t)((lane >> 4) * 8 + (lane & 7)) * TSTRIDE + (uint32_t)((lane >> 3) & 1) * 16;

#pragma unroll
  for (int mi = 0; mi < 2; mi++)
#pragma unroll
    for (int ni = 0; ni < 8; ni++)
#pragma unroll
      for (int r = 0; r < 4; r++) acc[mi][ni][r] = 0.f;

  for (int kt = 0; kt < 16; kt++) {
    const int k0 = kt * 64;
    __syncthreads();
    load_tile(Ah, m0, k0, sm + OFF_AH, tid);
    load_tile(Al, m0, k0, sm + OFF_AL, tid);
    load_tile(Bh, n0, k0, sm + OFF_BH, tid);
    load_tile(Bl, n0, k0, sm + OFF_BL, tid);
    __syncthreads();

#pragma unroll
    for (int ks = 0; ks < 4; ks++) {
      const uint32_t koff = (uint32_t)ks * 32;  // 16 bf16 = 32 bytes
      uint32_t ah[2][4], al[2][4];
#pragma unroll
      for (int mi = 0; mi < 2; mi++) {
        const uint32_t arow = (uint32_t)(m_base + mi * 16) * TSTRIDE + koff + a_lane;
        ldsm_x4(ah[mi][0], ah[mi][1], ah[mi][2], ah[mi][3], sbase + OFF_AH + arow);
        ldsm_x4(al[mi][0], al[mi][1], al[mi][2], al[mi][3], sbase + OFF_AL + arow);
      }
#pragma unroll
      for (int nip = 0; nip < 4; nip++) {
        const uint32_t brow = (uint32_t)(n_base + nip * 16) * TSTRIDE + koff + b_lane;
        uint32_t bh0, bh1, bh2, bh3, bl0, bl1, bl2, bl3;
        ldsm_x4(bh0, bh1, bh2, bh3, sbase + OFF_BH + brow);
        ldsm_x4(bl0, bl1, bl2, bl3, sbase + OFF_BL + brow);
#pragma unroll
        for (int mi = 0; mi < 2; mi++) {
          mma16816(acc[mi][nip * 2 + 0], ah[mi], bh0, bh1);
          mma16816(acc[mi][nip * 2 + 0], ah[mi], bl0, bl1);
          mma16816(acc[mi][nip * 2 + 0], al[mi], bh0, bh1);
          mma16816(acc[mi][nip * 2 + 1], ah[mi], bh2, bh3);
          mma16816(acc[mi][nip * 2 + 1], ah[mi], bl2, bl3);
          mma16816(acc[mi][nip * 2 + 1], al[mi], bh2, bh3);
        }
      }
    }
  }
}

// ---------------------------------------------------------------------------
// QKV GEMM: scatter epilogue into fp32 Q/K/V (s,b,h,t,d).
// n -> dd*48 + kc*16 + h
// ---------------------------------------------------------------------------
__global__ __launch_bounds__(256) void qkv_mma() {
  extern __shared__ char sm[];
  const int s = blockIdx.z;
  const int n0 = blockIdx.x * 128;
  const int m0 = blockIdx.y * 128;

  float acc[2][8][4];
  mma_mainloop(g_xy_h + (size_t)s * NM * NE, g_xy_l + (size_t)s * NM * NE,
               g_wq_h + (size_t)s * NE3 * NE, g_wq_l + (size_t)s * NE3 * NE,
               m0, n0, sm, acc);

  const int tid = threadIdx.x;
  const int lane = tid & 31;
  const int w = tid >> 5;
  const int m_base = m0 + (w >> 1) * 32;
  const int n_base = n0 + (w & 1) * 64;
  const int r_lo = lane >> 2;
  const int c0 = (lane & 3) * 2;

#pragma unroll
  for (int mi = 0; mi < 2; mi++) {
#pragma unroll
    for (int ni = 0; ni < 8; ni++) {
#pragma unroll
      for (int rr = 0; rr < 2; rr++) {
        const int m = m_base + mi * 16 + r_lo + rr * 8;
        const int bb = m >> 10;
        const int t = m & 1023;
#pragma unroll
        for (int cc = 0; cc < 2; cc++) {
          const int n = n_base + ni * 8 + c0 + cc;
          const int dd = n / 48;
          const int rem = n - dd * 48;
          const int kc = rem >> 4;
          const int h = rem & 15;
          float* base = (kc == 0) ? G_Q : (kc == 1) ? G_K : G_V;
          base[((((size_t)s * NB + bb) * NH + h) * NT + t) * ND + dd] =
              acc[mi][ni][rr * 2 + cc];
        }
      }
    }
  }
}

// ---------------------------------------------------------------------------
// Out-projection GEMM: plain store epilogue.
// ---------------------------------------------------------------------------
__global__ __launch_bounds__(256) void proj_mma(float* __restrict__ out) {
  extern __shared__ char sm[];
  const int s = blockIdx.z;
  const int n0 = blockIdx.x * 128;
  const int m0 = blockIdx.y * 128;

  float acc[2][8][4];
  mma_mainloop(g_ao_h + (size_t)s * NM * NE, g_ao_l + (size_t)s * NM * NE,
               g_wo_h + (size_t)s * NE * NE, g_wo_l + (size_t)s * NE * NE,
               m0, n0, sm, acc);

  const int tid = threadIdx.x;
  const int lane = tid & 31;
  const int w = tid >> 5;
  const int m_base = m0 + (w >> 1) * 32;
  const int n_base = n0 + (w & 1) * 64;
  const int r_lo = lane >> 2;
  const int c0 = (lane & 3) * 2;

  float* obase = out + (size_t)s * NM * NE;
#pragma unroll
  for (int mi = 0; mi < 2; mi++) {
#pragma unroll
    for (int rr = 0; rr < 2; rr++) {
      const int m = m_base + mi * 16 + r_lo + rr * 8;
      float* orow = obase + (size_t)m * NE + n_base;
#pragma unroll
      for (int ni = 0; ni < 8; ni++) {
        float2 v;
        v.x = acc[mi][ni][rr * 2 + 0];
        v.y = acc[mi][ni][rr * 2 + 1];
        *(float2*)(orow + ni * 8 + c0) = v;
      }
    }
  }
}

// ---------------------------------------------------------------------------
// Flash attention (fp32 SIMT). Epilogue writes bf16 hi/lo into g_ao (flat).
// ---------------------------------------------------------------------------
#define BC 32

__global__ __launch_bounds__(256) void attn_kernel() {
  __shared__ float Qs[64 * 68];
  __shared__ float Ks[BC * 68];
  __shared__ float Ps[64 * 36];
  __shared__ float Vs[BC * 64];

  const int s = blockIdx.z;
  const int bh = blockIdx.y;
  const int bb = bh >> 4;
  const int h = bh & 15;
  const int q0 = blockIdx.x * 64;

  const size_t qoff = (((size_t)(1 - s) * NB + bb) * NH + h) * NT * ND;
  const size_t kvoff = (((size_t)s * NB + bb) * NH + h) * NT * ND;
  const float* __restrict__ Qg = G_Q + qoff;
  const float* __restrict__ Kg = G_K + kvoff;
  const float* __restrict__ Vg = G_V + kvoff;

  const int tid = threadIdx.x;
  const int row = tid >> 2;
  const int part = tid & 3;
  const int krow = tid >> 3;
  const int kcol = (tid & 7) * 8;

  {
    const float4* src = (const float4*)&Qg[(size_t)(q0 + row) * ND + part * 16];
    float4* dst = (float4*)&Qs[row * 68 + part * 16];
    dst[0] = src[0]; dst[1] = src[1]; dst[2] = src[2]; dst[3] = src[3];
  }
  __syncthreads();

  float m_i = -1e30f;
  float l_i = 0.f;
  float acc[16];
#pragma unroll
  for (int i = 0; i < 16; i++) acc[i] = 0.f;

  for (int kt = 0; kt < NT / BC; kt++) {
    {
      const float4* ksrc = (const float4*)&Kg[(size_t)(kt * BC + krow) * ND + kcol];
      float4* kdst = (float4*)&Ks[krow * 68 + kcol];
      kdst[0] = ksrc[0]; kdst[1] = ksrc[1];
      const float4* vsrc = (const float4*)&Vg[(size_t)(kt * BC + krow) * ND + kcol];
      float4* vdst = (float4*)&Vs[krow * 64 + kcol];
      vdst[0] = vsrc[0]; vdst[1] = vsrc[1];
    }
    __syncthreads();

    float sv[8];
    const float4* qr = (const float4*)&Qs[row * 68];
#pragma unroll
    for (int jc = 0; jc < 8; jc++) {
      const int j = jc * 4 + part;
      const float4* kr = (const float4*)&Ks[j * 68];
      float sum = 0.f;
#pragma unroll
      for (int d4 = 0; d4 < 16; d4++) {
        float4 qa = qr[d4];
        float4 kb = kr[d4];
        sum += qa.x * kb.x + qa.y * kb.y + qa.z * kb.z + qa.w * kb.w;
      }
      sv[jc] = sum * 0.125f;
    }

    float mloc = sv[0];
#pragma unroll
    for (int jc = 1; jc < 8; jc++) mloc = fmaxf(mloc, sv[jc]);
    mloc = fmaxf(mloc, __shfl_xor_sync(0xffffffffu, mloc, 1));
    mloc = fmaxf(mloc, __shfl_xor_sync(0xffffffffu, mloc, 2));
    const float m_new = fmaxf(m_i, mloc);

    float psum = 0.f;
#pragma unroll
    for (int jc = 0; jc < 8; jc++) {
      float p = __expf(sv[jc] - m_new);
      Ps[row * 36 + jc * 4 + part] = p;
      psum += p;
    }
    psum += __shfl_xor_sync(0xffffffffu, psum, 1);
    psum += __shfl_xor_sync(0xffffffffu, psum, 2);

    const float alpha = __expf(m_i - m_new);
    m_i = m_new;
    l_i = l_i * alpha + psum;
#pragma unroll
    for (int i = 0; i < 16; i++) acc[i] *= alpha;
    __syncwarp();

#pragma unroll 8
    for (int j = 0; j < BC; j++) {
      float p = Ps[row * 36 + j];
      const float4* vr = (const float4*)&Vs[j * 64 + part * 16];
      float4 v0 = vr[0], v1 = vr[1], v2 = vr[2], v3 = vr[3];
      acc[0]  += p * v0.x; acc[1]  += p * v0.y; acc[2]  += p * v0.z; acc[3]  += p * v0.w;
      acc[4]  += p * v1.x; acc[5]  += p * v1.y; acc[6]  += p * v1.z; acc[7]  += p * v1.w;
      acc[8]  += p * v2.x; acc[9]  += p * v2.y; acc[10] += p * v2.z; acc[11] += p * v2.w;
      acc[12] += p * v3.x; acc[13] += p * v3.y; acc[14] += p * v3.z; acc[15] += p * v3.w;
    }
    __syncthreads();
  }

  const float inv = 1.f / l_i;
  const size_t mrow = (size_t)bb * NT + (q0 + row);
  const size_t base = ((size_t)s * NM + mrow) * NE + h * 64 + part * 16;
#pragma unroll
  for (int i = 0; i < 16; i++) {
    float v = acc[i] * inv;
    __nv_bfloat16 hi = __float2bfloat16(v);
    g_ao_h[base + i] = hi;
    g_ao_l[base + i] = __float2bfloat16(v - __bfloat162float(hi));
  }
}

// ---------------------------------------------------------------------------

extern "C" void kernel_launch(void* const* d_in, const int* in_sizes, int n_in,
                              void* d_out, int out_size) {
  const float* x = (const float*)d_in[0];
  const float* y = (const float*)d_in[1];
  const float* Wqkv1 = (const float*)d_in[2];
  const float* Wqkv2 = (const float*)d_in[3];
  const float* Wout1 = (const float*)d_in[4];
  const float* Wout2 = (const float*)d_in[5];
  float* out = (float*)d_out;

  cudaFuncSetAttribute(qkv_mma, cudaFuncAttributeMaxDynamicSharedMemorySize, GEMM_SMEM);
  cudaFuncSetAttribute(proj_mma, cudaFuncAttributeMaxDynamicSharedMemorySize, GEMM_SMEM);

  __nv_bfloat16 *xyh, *xyl, *wqh, *wql, *woh, *wol;
  cudaGetSymbolAddress((void**)&xyh, g_xy_h);
  cudaGetSymbolAddress((void**)&xyl, g_xy_l);
  cudaGetSymbolAddress((void**)&wqh, g_wq_h);
  cudaGetSymbolAddress((void**)&wql, g_wq_l);
  cudaGetSymbolAddress((void**)&woh, g_wo_h);
  cudaGetSymbolAddress((void**)&wol, g_wo_l);

  const int nxy = NM * NE;
  const int nwq = NE3 * NE;
  const int nwo = NE * NE;

  convert_split<<<(nxy + 255) / 256, 256>>>(x, xyh, xyl, nxy);
  convert_split<<<(nxy + 255) / 256, 256>>>(y, xyh + nxy, xyl + nxy, nxy);
  convert_split<<<(nwq + 255) / 256, 256>>>(Wqkv1, wqh, wql, nwq);
  convert_split<<<(nwq + 255) / 256, 256>>>(Wqkv2, wqh + nwq, wql + nwq, nwq);
  convert_split<<<(nwo + 255) / 256, 256>>>(Wout1, woh, wol, nwo);
  convert_split<<<(nwo + 255) / 256, 256>>>(Wout2, woh + nwo, wol + nwo, nwo);

  qkv_mma<<<dim3(NE3 / 128, NM / 128, 2), 256, GEMM_SMEM>>>();
  attn_kernel<<<dim3(NT / 64, NB * NH, 2), 256>>>();
  proj_mma<<<dim3(NE / 128, NM / 128, 2), 256, GEMM_SMEM>>>(out);
}